// round 3
// baseline (speedup 1.0000x reference)
#include <cuda_runtime.h>
#include <math.h>

#define KB_ 4
#define KT_ 4096
#define KDIM_ 64
#define KHID_ 256
#define KROWS_ (KB_ * KT_)   // 16384
#define HIST_ 128

__device__ float g_h[KROWS_ * KHID_];
__device__ float g_ln[KROWS_ * KHID_];
__device__ float g_qkv[KROWS_ * 3 * KHID_];
__device__ float g_m1[KROWS_ * KHID_];

// ---------------------------------------------------------------------------
// Packed fp32x2 helpers
// ---------------------------------------------------------------------------
__device__ __forceinline__ unsigned long long ffma2(unsigned long long a,
                                                    unsigned long long b,
                                                    unsigned long long c) {
    unsigned long long d;
    asm("fma.rn.f32x2 %0, %1, %2, %3;" : "=l"(d) : "l"(a), "l"(b), "l"(c));
    return d;
}
__device__ __forceinline__ unsigned long long pack2(float x, float y) {
    unsigned long long r;
    asm("mov.b64 %0, {%1, %2};" : "=l"(r) : "f"(x), "f"(y));
    return r;
}
__device__ __forceinline__ float2 unpack2(unsigned long long r) {
    float2 v;
    asm("mov.b64 {%0, %1}, %2;" : "=f"(v.x), "=f"(v.y) : "l"(r));
    return v;
}

// ---------------------------------------------------------------------------
// GEMM v3: out[M,N] = A[M,K] @ W[K,N] + bias (+gelu | +residual)
// BM=128, BK=16, BN=64*NJ, 256 threads (8 warps).
// Warp w owns m-rows w*16..w*16+15 as 8 genuine FFMA2 pairs (acc along m).
// Lane tx owns n-cols {n0 + 32c + tx}. B stored DUPLICATED in smem:
//   Bsd[k][c*64 + 2*tx] = (b,b) for n = 32c+tx  -> conflict-free LDS.64,
// A read as warp-uniform broadcast LDS.128 (1 crossbar cyc each).
// Inner loop: 4 brcLDS.128 + 2NJ LDS.64 + 8*2NJ FFMA2 per kk -> FMA-bound.
// EPI: 0 = bias, 1 = bias+gelu(exact), 2 = bias+residual
// ---------------------------------------------------------------------------
template <int NJ, int EPI>
__global__ __launch_bounds__(256, 2)
void gemm3_k(const float* __restrict__ A, const float* __restrict__ W,
             const float* __restrict__ bias, const float* __restrict__ res,
             float* __restrict__ out, int M, int K, int N)
{
    constexpr int BM = 128, BK = 16;
    constexpr int BN = 64 * NJ;
    constexpr int NC = 2 * NJ;         // n-cols per lane
    constexpr int AP = BM + 4;         // 132 (16B-aligned rows, low store conflicts)
    constexpr int BP = 2 * BN;         // duplicated row pitch
    __shared__ float As[BK * AP];
    __shared__ float Bsd[BK * BP];

    const int tid = threadIdx.x;
    const int tx  = tid & 31;
    const int w   = tid >> 5;
    const int m0  = blockIdx.y * BM;
    const int n0  = blockIdx.x * BN;

    // A gmem: thread -> (row am, 8 consecutive k starting at ak0)
    const int am  = tid >> 1;
    const int ak0 = (tid & 1) * 8;
    const float* Ag = A + (size_t)(m0 + am) * K + ak0;

    // B gmem: NJ float4 per thread
    int br[NJ], bc4[NJ];
#pragma unroll
    for (int q = 0; q < NJ; q++) {
        const int f = tid + 256 * q;
        br[q]  = f / (BN / 4);
        bc4[q] = f % (BN / 4);
    }

    unsigned long long acc2[8][NC];
#pragma unroll
    for (int p = 0; p < 8; p++)
#pragma unroll
        for (int c = 0; c < NC; c++) acc2[p][c] = 0ull;

    // ---- prologue: load tile 0 ----
    float4 a0 = *(const float4*)(Ag);
    float4 a1 = *(const float4*)(Ag + 4);
    float4 bv[NJ];
#pragma unroll
    for (int q = 0; q < NJ; q++)
        bv[q] = *(const float4*)&W[(size_t)br[q] * N + n0 + 4 * bc4[q]];

    // store helpers (inline)
    {
        float ta[8] = {a0.x, a0.y, a0.z, a0.w, a1.x, a1.y, a1.z, a1.w};
#pragma unroll
        for (int c = 0; c < 8; c++) As[(ak0 + c) * AP + am] = ta[c];
#pragma unroll
        for (int q = 0; q < NJ; q++) {
            float tb[4] = {bv[q].x, bv[q].y, bv[q].z, bv[q].w};
#pragma unroll
            for (int e = 0; e < 4; e++) {
                const int nl = 4 * bc4[q] + e;
                *(float2*)&Bsd[br[q] * BP + (nl >> 5) * 64 + 2 * (nl & 31)] =
                    make_float2(tb[e], tb[e]);
            }
        }
    }
    __syncthreads();

    const int ntile = K / BK;
    for (int kt = 0; kt < ntile; kt++) {
        if (kt + 1 < ntile) {   // register prefetch of next tile
            a0 = *(const float4*)(Ag + (kt + 1) * BK);
            a1 = *(const float4*)(Ag + (kt + 1) * BK + 4);
#pragma unroll
            for (int q = 0; q < NJ; q++)
                bv[q] = *(const float4*)
                    &W[(size_t)((kt + 1) * BK + br[q]) * N + n0 + 4 * bc4[q]];
        }
#pragma unroll
        for (int kk = 0; kk < BK; kk++) {
            unsigned long long af2[8];
#pragma unroll
            for (int c = 0; c < 4; c++) {
                ulonglong2 t2 = *(const ulonglong2*)&As[kk * AP + w * 16 + 4 * c];
                af2[2 * c]     = t2.x;
                af2[2 * c + 1] = t2.y;
            }
            unsigned long long bd2[NC];
#pragma unroll
            for (int c = 0; c < NC; c++)
                bd2[c] = *(const unsigned long long*)&Bsd[kk * BP + c * 64 + 2 * tx];
#pragma unroll
            for (int p = 0; p < 8; p++)
#pragma unroll
                for (int c = 0; c < NC; c++)
                    acc2[p][c] = ffma2(af2[p], bd2[c], acc2[p][c]);
        }
        __syncthreads();
        if (kt + 1 < ntile) {
            float ta[8] = {a0.x, a0.y, a0.z, a0.w, a1.x, a1.y, a1.z, a1.w};
#pragma unroll
            for (int c = 0; c < 8; c++) As[(ak0 + c) * AP + am] = ta[c];
#pragma unroll
            for (int q = 0; q < NJ; q++) {
                float tb[4] = {bv[q].x, bv[q].y, bv[q].z, bv[q].w};
#pragma unroll
                for (int e = 0; e < 4; e++) {
                    const int nl = 4 * bc4[q] + e;
                    *(float2*)&Bsd[br[q] * BP + (nl >> 5) * 64 + 2 * (nl & 31)] =
                        make_float2(tb[e], tb[e]);
                }
            }
            __syncthreads();
        }
    }

    // ---- epilogue: coalesced scalar stores (lanes span contiguous n) ----
#pragma unroll
    for (int c = 0; c < NC; c++) {
        const int n = n0 + 32 * c + tx;
        const float bn = bias[n];
#pragma unroll
        for (int p = 0; p < 8; p++) {
            const int m = m0 + w * 16 + 2 * p;
            float2 v = unpack2(acc2[p][c]);
            v.x += bn; v.y += bn;
            if (EPI == 1) {
                v.x = 0.5f * v.x * (1.f + erff(v.x * 0.70710678118654752f));
                v.y = 0.5f * v.y * (1.f + erff(v.y * 0.70710678118654752f));
            }
            if (EPI == 2) {
                v.x += res[(size_t)m * N + n];
                v.y += res[(size_t)(m + 1) * N + n];
            }
            out[(size_t)m * N + n]       = v.x;
            out[(size_t)(m + 1) * N + n] = v.y;
        }
    }
}

// ---------------------------------------------------------------------------
// LayerNorm: one warp per 256-wide row
// ---------------------------------------------------------------------------
__global__ __launch_bounds__(256)
void ln_k(const float* __restrict__ x, const float* __restrict__ g,
          const float* __restrict__ b, float* __restrict__ y)
{
    const int wid = threadIdx.x >> 5;
    const int lane = threadIdx.x & 31;
    const int row = blockIdx.x * 8 + wid;
    const float* xr = x + (size_t)row * KHID_;

    float v[8];
    float s = 0.f, s2 = 0.f;
#pragma unroll
    for (int i = 0; i < 8; i++) {
        v[i] = xr[lane + 32 * i];
        s += v[i];
        s2 += v[i] * v[i];
    }
#pragma unroll
    for (int o = 16; o; o >>= 1) {
        s += __shfl_xor_sync(0xffffffffu, s, o);
        s2 += __shfl_xor_sync(0xffffffffu, s2, o);
    }
    const float mu = s * (1.f / 256.f);
    const float var = s2 * (1.f / 256.f) - mu * mu;
    const float r = rsqrtf(var + 1e-5f);
    float* yr = y + (size_t)row * KHID_;
#pragma unroll
    for (int i = 0; i < 8; i++) {
        const int d = lane + 32 * i;
        yr[d] = (v[i] - mu) * r * g[d] + b[d];
    }
}

// ---------------------------------------------------------------------------
// Windowed attention (HISTORY=128). 64 queries/block, FFMA2, vectorized
// conflict-aware smem layouts:
//   Qs [64 rows][132]           (d-major rows; broadcast LDS.128 gets 2 d-pairs)
//   Ks2[64 d-pairs][132]        Ks2[t][2*key+b] = K[key][2t+b]
//                               -> LDS.128 gives pair t for keys 2tx,2tx+1
//   P  [64][196]                (overlaps Qs+Ks2)
//   Vs [64 keys][132]           lane owns 4 dims -> 16B conflict-free loads
// ---------------------------------------------------------------------------
#define ATTN_SMEM_FLOATS (16896 + 8448)

__global__ __launch_bounds__(256, 2)
void attn_k(const float* __restrict__ qkv, float* __restrict__ h)
{
    extern __shared__ float sm[];
    float* Qs  = sm;               // 8448
    float* Ks2 = sm + 8448;        // 8448
    float* P   = sm;               // 64*196 = 12544 (overlaps Qs+Ks2)
    float* Vs  = sm + 16896;       // 8448

    const int tid = threadIdx.x;
    const int tx = tid & 31;
    const int ty = tid >> 5;
    const int b  = blockIdx.x >> 6;
    const int qt = blockIdx.x & 63;
    const int t0 = qt * 64;
    const int g0 = b * KT_ + t0;
    const int kstart = (t0 >= HIST_) ? (t0 - HIST_) : 0;
    const int ntiles = (t0 + 64 - kstart) >> 6;

    const int lc  = tid & 127;
    const int lr0 = (tid >> 7) * 32;
    const int lt  = lc >> 1;          // d-pair index for K loader
    const int lb  = lc & 1;
    const float scale = 0.0625f;

    float sreg[3][8][2];

    // ---------------- QK^T ----------------
#pragma unroll
    for (int kt = 0; kt < 3; kt++) {
        if (kt < ntiles) {
            const int kg0 = b * KT_ + kstart + kt * 64;
            unsigned long long acc2[8][2];
#pragma unroll
            for (int i = 0; i < 8; i++) { acc2[i][0] = 0ull; acc2[i][1] = 0ull; }

#pragma unroll
            for (int half = 0; half < 2; half++) {
                __syncthreads();
                for (int rr = 0; rr < 32; rr++) {
                    const int r = lr0 + rr;
                    Qs[r * 132 + lc] =
                        qkv[(size_t)(g0 + r) * 768 + half * 128 + lc] * scale;
                    Ks2[lt * 132 + 2 * r + lb] =
                        qkv[(size_t)(kg0 + r) * 768 + 256 + half * 128 + lc];
                }
                __syncthreads();
#pragma unroll 4
                for (int t = 0; t < 64; t += 2) {
                    ulonglong2 kv0 = *(const ulonglong2*)&Ks2[t * 132 + 4 * tx];
                    ulonglong2 kv1 = *(const ulonglong2*)&Ks2[(t + 1) * 132 + 4 * tx];
#pragma unroll
                    for (int i = 0; i < 8; i++) {
                        ulonglong2 qv =
                            *(const ulonglong2*)&Qs[(ty * 8 + i) * 132 + 2 * t];
                        acc2[i][0] = ffma2(qv.x, kv0.x, acc2[i][0]);
                        acc2[i][1] = ffma2(qv.x, kv0.y, acc2[i][1]);
                        acc2[i][0] = ffma2(qv.y, kv1.x, acc2[i][0]);
                        acc2[i][1] = ffma2(qv.y, kv1.y, acc2[i][1]);
                    }
                }
            }
#pragma unroll
            for (int i = 0; i < 8; i++) {
#pragma unroll
                for (int j = 0; j < 2; j++) {
                    float2 v = unpack2(acc2[i][j]);
                    const float s = v.x + v.y;
                    const int q = t0 + ty * 8 + i;
                    const int k = kstart + kt * 64 + 2 * tx + j;
                    const int d = q - k;
                    sreg[kt][i][j] = (d >= 0 && d <= HIST_) ? s : -3.0e38f;
                }
            }
        }
    }
    __syncthreads();

    // ---------------- softmax in registers ----------------
#pragma unroll
    for (int i = 0; i < 8; i++) {
        float mx = -3.0e38f;
#pragma unroll
        for (int kt = 0; kt < 3; kt++)
            if (kt < ntiles) {
                mx = fmaxf(mx, sreg[kt][i][0]);
                mx = fmaxf(mx, sreg[kt][i][1]);
            }
#pragma unroll
        for (int o = 16; o; o >>= 1)
            mx = fmaxf(mx, __shfl_xor_sync(0xffffffffu, mx, o));
        float sum = 0.f;
#pragma unroll
        for (int kt = 0; kt < 3; kt++)
            if (kt < ntiles) {
                const float e0 = __expf(sreg[kt][i][0] - mx);
                const float e1 = __expf(sreg[kt][i][1] - mx);
                sreg[kt][i][0] = e0;
                sreg[kt][i][1] = e1;
                sum += e0 + e1;
            }
#pragma unroll
        for (int o = 16; o; o >>= 1)
            sum += __shfl_xor_sync(0xffffffffu, sum, o);
        const float rinv = 1.0f / sum;
#pragma unroll
        for (int kt = 0; kt < 3; kt++)
            if (kt < ntiles) {
                float2 pv;
                pv.x = sreg[kt][i][0] * rinv;
                pv.y = sreg[kt][i][1] * rinv;
                *(float2*)&P[(ty * 8 + i) * 196 + kt * 64 + 2 * tx] = pv;
            }
    }

    // ---------------- O = P V, residual fused ----------------
#pragma unroll
    for (int half = 0; half < 2; half++) {
        unsigned long long o2[8][2];
#pragma unroll
        for (int i = 0; i < 8; i++) { o2[i][0] = 0ull; o2[i][1] = 0ull; }

        for (int kt = 0; kt < ntiles; kt++) {
            const int kg0 = b * KT_ + kstart + kt * 64;
            __syncthreads();
            for (int rr = 0; rr < 32; rr++) {
                const int r = lr0 + rr;
                Vs[r * 132 + lc] =
                    qkv[(size_t)(kg0 + r) * 768 + 512 + half * 128 + lc];
            }
            __syncthreads();
#pragma unroll 2
            for (int jj = 0; jj < 64; jj += 4) {
                ulonglong2 vv0 = *(const ulonglong2*)&Vs[(jj + 0) * 132 + 4 * tx];
                ulonglong2 vv1 = *(const ulonglong2*)&Vs[(jj + 1) * 132 + 4 * tx];
                ulonglong2 vv2 = *(const ulonglong2*)&Vs[(jj + 2) * 132 + 4 * tx];
                ulonglong2 vv3 = *(const ulonglong2*)&Vs[(jj + 3) * 132 + 4 * tx];
#pragma unroll
                for (int i = 0; i < 8; i++) {
                    float4 p4 = *(const float4*)&P[(ty * 8 + i) * 196 + kt * 64 + jj];
                    unsigned long long p2;
                    p2 = pack2(p4.x, p4.x);
                    o2[i][0] = ffma2(p2, vv0.x, o2[i][0]);
                    o2[i][1] = ffma2(p2, vv0.y, o2[i][1]);
                    p2 = pack2(p4.y, p4.y);
                    o2[i][0] = ffma2(p2, vv1.x, o2[i][0]);
                    o2[i][1] = ffma2(p2, vv1.y, o2[i][1]);
                    p2 = pack2(p4.z, p4.z);
                    o2[i][0] = ffma2(p2, vv2.x, o2[i][0]);
                    o2[i][1] = ffma2(p2, vv2.y, o2[i][1]);
                    p2 = pack2(p4.w, p4.w);
                    o2[i][0] = ffma2(p2, vv3.x, o2[i][0]);
                    o2[i][1] = ffma2(p2, vv3.y, o2[i][1]);
                }
            }
        }
#pragma unroll
        for (int i = 0; i < 8; i++) {
            const size_t base =
                (size_t)(g0 + ty * 8 + i) * KHID_ + half * 128 + tx * 4;
            float4 hv = *(const float4*)&h[base];
            float2 a0 = unpack2(o2[i][0]);
            float2 a1 = unpack2(o2[i][1]);
            hv.x += a0.x; hv.y += a0.y; hv.z += a1.x; hv.w += a1.y;
            *(float4*)&h[base] = hv;
        }
    }
}

// ---------------------------------------------------------------------------
// Launch
// ---------------------------------------------------------------------------
extern "C" void kernel_launch(void* const* d_in, const int* in_sizes, int n_in,
                              void* d_out, int out_size)
{
    (void)in_sizes; (void)n_in; (void)out_size;
    const float* x       = (const float*)d_in[0];
    const float* W_in    = (const float*)d_in[1];
    const float* b_in    = (const float*)d_in[2];
    const float* W_qkv   = (const float*)d_in[3];
    const float* b_qkv   = (const float*)d_in[4];
    const float* g_attn  = (const float*)d_in[5];
    const float* be_attn = (const float*)d_in[6];
    const float* g_mlp   = (const float*)d_in[7];
    const float* be_mlp  = (const float*)d_in[8];
    const float* W1      = (const float*)d_in[9];
    const float* b1      = (const float*)d_in[10];
    const float* W2      = (const float*)d_in[11];
    const float* b2      = (const float*)d_in[12];
    const float* W_out   = (const float*)d_in[13];
    const float* b_out   = (const float*)d_in[14];
    float* out = (float*)d_out;

    float *h_p, *ln_p, *qkv_p, *m1_p;
    cudaGetSymbolAddress((void**)&h_p, g_h);
    cudaGetSymbolAddress((void**)&ln_p, g_ln);
    cudaGetSymbolAddress((void**)&qkv_p, g_qkv);
    cudaGetSymbolAddress((void**)&m1_p, g_m1);

    const int attn_smem = ATTN_SMEM_FLOATS * 4;   // 101376 B
    cudaFuncSetAttribute((const void*)attn_k,
                         cudaFuncAttributeMaxDynamicSharedMemorySize, attn_smem);

    const dim3 blk(256);

    // 1) h = x @ W_in + b_in
    gemm3_k<2, 0><<<dim3(KHID_ / 128, KROWS_ / 128), blk>>>(
        x, W_in, b_in, nullptr, h_p, KROWS_, KDIM_, KHID_);

    // 2) ln = LN(h; g_attn, be_attn)
    ln_k<<<KROWS_ / 8, blk>>>(h_p, g_attn, be_attn, ln_p);

    // 3) qkv = ln @ W_qkv + b_qkv
    gemm3_k<2, 0><<<dim3(3 * KHID_ / 128, KROWS_ / 128), blk>>>(
        ln_p, W_qkv, b_qkv, nullptr, qkv_p, KROWS_, KHID_, 3 * KHID_);

    // 4) h += window_attention(qkv)
    attn_k<<<KB_ * (KT_ / 64), blk, attn_smem>>>(qkv_p, h_p);

    // 5) ln = LN(h; g_mlp, be_mlp)
    ln_k<<<KROWS_ / 8, blk>>>(h_p, g_mlp, be_mlp, ln_p);

    // 6) m1 = gelu(ln @ W1 + b1)
    gemm3_k<2, 1><<<dim3(KHID_ / 128, KROWS_ / 128), blk>>>(
        ln_p, W1, b1, nullptr, m1_p, KROWS_, KHID_, KHID_);

    // 7) h = h + (m1 @ W2 + b2)
    gemm3_k<2, 2><<<dim3(KHID_ / 128, KROWS_ / 128), blk>>>(
        m1_p, W2, b2, h_p, h_p, KROWS_, KHID_, KHID_);

    // 8) out = h @ W_out + b_out
    gemm3_k<1, 0><<<dim3(KDIM_ / 64, KROWS_ / 128), blk>>>(
        h_p, W_out, b_out, nullptr, out, KROWS_, KHID_, KDIM_);
}

// round 5
// speedup vs baseline: 1.7419x; 1.7419x over previous
#include <cuda_runtime.h>
#include <cuda_bf16.h>
#include <math.h>
#include <stdint.h>

#define KB_ 4
#define KT_ 4096
#define KDIM_ 64
#define KHID_ 256
#define KROWS_ (KB_ * KT_)   // 16384
#define HIST_ 128

// Scratch (device globals; no allocation allowed)
__device__ float g_h[KROWS_ * KHID_];
__device__ float g_ln[KROWS_ * KHID_];
__device__ float g_qkv[KROWS_ * 3 * KHID_];
__device__ float g_m1[KROWS_ * KHID_];
// split-bf16 transposed weights: [N][K] hi/lo
#define OFF_IN_  0
#define OFF_QKV_ 16384
#define OFF_W1_  212992
#define OFF_W2_  278528
#define OFF_OUT_ 344064
#define WSPLIT_TOT_ 360448
__device__ __nv_bfloat16 g_whi[WSPLIT_TOT_];
__device__ __nv_bfloat16 g_wlo[WSPLIT_TOT_];

// ---------------------------------------------------------------------------
// PTX helpers (all plain sm_80-era features -> compile for compute_103)
// ---------------------------------------------------------------------------
__device__ __forceinline__ uint32_t smem_u32(const void* p) {
    uint32_t a;
    asm("{ .reg .u64 t; cvta.to.shared.u64 t, %1; cvt.u32.u64 %0, t; }"
        : "=r"(a) : "l"(p));
    return a;
}
__device__ __forceinline__ void ldsm4(uint32_t* r, uint32_t a) {
    asm volatile("ldmatrix.sync.aligned.m8n8.x4.shared.b16 {%0,%1,%2,%3}, [%4];"
        : "=r"(r[0]), "=r"(r[1]), "=r"(r[2]), "=r"(r[3]) : "r"(a));
}
__device__ __forceinline__ void mma_bf16(float* d, const uint32_t* a,
                                         const uint32_t* b) {
    asm volatile(
        "mma.sync.aligned.m16n8k16.row.col.f32.bf16.bf16.f32 "
        "{%0,%1,%2,%3}, {%4,%5,%6,%7}, {%8,%9}, {%0,%1,%2,%3};"
        : "+f"(d[0]), "+f"(d[1]), "+f"(d[2]), "+f"(d[3])
        : "r"(a[0]), "r"(a[1]), "r"(a[2]), "r"(a[3]), "r"(b[0]), "r"(b[1]));
}
// packed fp32x2 (attention)
__device__ __forceinline__ unsigned long long ffma2(unsigned long long a,
                                                    unsigned long long b,
                                                    unsigned long long c) {
    unsigned long long d;
    asm("fma.rn.f32x2 %0, %1, %2, %3;" : "=l"(d) : "l"(a), "l"(b), "l"(c));
    return d;
}
__device__ __forceinline__ unsigned long long pack2(float x, float y) {
    unsigned long long r;
    asm("mov.b64 %0, {%1, %2};" : "=l"(r) : "f"(x), "f"(y));
    return r;
}
__device__ __forceinline__ float2 unpack2(unsigned long long r) {
    float2 v;
    asm("mov.b64 {%0, %1}, %2;" : "=f"(v.x), "=f"(v.y) : "l"(r));
    return v;
}

// ---------------------------------------------------------------------------
// Weight split: W[K,N] fp32 -> hi/lo [N,K] bf16 (transposed)
// ---------------------------------------------------------------------------
__global__ __launch_bounds__(256)
void wsplit_k(const float* __restrict__ W, __nv_bfloat16* __restrict__ hi,
              __nv_bfloat16* __restrict__ lo, int K, int N)
{
    const int idx = blockIdx.x * 256 + threadIdx.x;
    if (idx >= K * N) return;
    const int k = idx / N, n = idx % N;
    const float a = W[idx];
    const __nv_bfloat16 h = __float2bfloat16_rn(a);
    const float r = a - __bfloat162float(h);
    hi[(size_t)n * K + k] = h;
    lo[(size_t)n * K + k] = __float2bfloat16_rn(r);
}

// ---------------------------------------------------------------------------
// HMMA GEMM (split-bf16, fp32 accum): out[M,64-tile] = A @ Wt^T + bias (+epi)
// CTA 128x64, 8 warps (4m x 2n), warp 32x32. K chunks of 64.
// Per k16 step: ldmatrix A hi/lo (2 m-sub) + B hi/lo (2 pair-loads),
// 24 HMMAs (HH, HL, LH). SW128 XOR swizzle -> conflict-free ldmatrix.
// EPI: 0 bias, 1 bias+gelu, 2 bias+residual
// ---------------------------------------------------------------------------
template <int EPI>
__global__ __launch_bounds__(256)
void gemm_mma(const float* __restrict__ A, const __nv_bfloat16* __restrict__ Bhi,
              const __nv_bfloat16* __restrict__ Blo, const float* __restrict__ bias,
              const float* __restrict__ res, float* __restrict__ out,
              int M, int K, int N)
{
    extern __shared__ char smp[];
    const uint32_t sb = smem_u32(smp);
    constexpr uint32_t A_HI = 0, A_LO = 16384, B_HI = 32768, B_LO = 40960;

    const int tid = threadIdx.x, lane = tid & 31, w = tid >> 5;
    const int wm = w & 3, wn = w >> 2;
    const int m0 = blockIdx.y * 128, n0 = blockIdx.x * 64;

    float acc[2][4][4];
#pragma unroll
    for (int mi = 0; mi < 2; mi++)
#pragma unroll
        for (int ni = 0; ni < 4; ni++)
#pragma unroll
            for (int e = 0; e < 4; e++) acc[mi][ni][e] = 0.f;

    const int a_row_l  = lane & 15;
    const int a_kseg_l = lane >> 4;
    const int b_row_l  = ((lane >> 4) << 3) + (lane & 7);
    const int b_kseg_l = (lane >> 3) & 1;

    const int nchunks = K >> 6;
    for (int c = 0; c < nchunks; c++) {
        __syncthreads();
        // ---- stage A chunk: fp32 -> hi/lo bf16, swizzled [128][64] ----
#pragma unroll
        for (int i = 0; i < 16; i++) {
            const int p = i * 256 + tid;
            const int row = p >> 5, kp = p & 31;
            float2 a = *(const float2*)&A[(size_t)(m0 + row) * K + c * 64 + 2 * kp];
            __nv_bfloat162 h2 = __floats2bfloat162_rn(a.x, a.y);
            const float rx = a.x - __bfloat162float(__low2bfloat16(h2));
            const float ry = a.y - __bfloat162float(__high2bfloat16(h2));
            __nv_bfloat162 l2 = __floats2bfloat162_rn(rx, ry);
            const uint32_t off = row * 128 + kp * 4;
            const uint32_t sw = off ^ ((off >> 3) & 0x70);
            *(__nv_bfloat162*)(smp + A_HI + sw) = h2;
            *(__nv_bfloat162*)(smp + A_LO + sw) = l2;
        }
        // ---- stage B chunk: pre-split bf16 [64 n-rows][64 k], swizzled ----
#pragma unroll
        for (int i = 0; i < 2; i++) {
            const int u = i * 256 + tid;
            const int row = u >> 3, seg = u & 7;
            const uint32_t off = row * 128 + seg * 16;
            const uint32_t sw = off ^ ((off >> 3) & 0x70);
            const size_t gsrc = (size_t)(n0 + row) * K + c * 64 + seg * 8;
            *(uint4*)(smp + B_HI + sw) = *(const uint4*)&Bhi[gsrc];
            *(uint4*)(smp + B_LO + sw) = *(const uint4*)&Blo[gsrc];
        }
        __syncthreads();

#pragma unroll
        for (int ks = 0; ks < 4; ks++) {
            uint32_t ah[2][4], al[2][4], bh[4][2], bl[4][2];
#pragma unroll
            for (int mi = 0; mi < 2; mi++) {
                const int row = wm * 32 + mi * 16 + a_row_l;
                const int kseg = ks * 2 + a_kseg_l;
                const uint32_t off = row * 128 + kseg * 16;
                const uint32_t sw = off ^ ((off >> 3) & 0x70);
                ldsm4(ah[mi], sb + A_HI + sw);
                ldsm4(al[mi], sb + A_LO + sw);
            }
#pragma unroll
            for (int np = 0; np < 2; np++) {
                const int row = wn * 32 + np * 16 + b_row_l;
                const int kseg = ks * 2 + b_kseg_l;
                const uint32_t off = row * 128 + kseg * 16;
                const uint32_t sw = off ^ ((off >> 3) & 0x70);
                uint32_t t[4];
                ldsm4(t, sb + B_HI + sw);
                bh[np * 2][0] = t[0]; bh[np * 2][1] = t[1];
                bh[np * 2 + 1][0] = t[2]; bh[np * 2 + 1][1] = t[3];
                ldsm4(t, sb + B_LO + sw);
                bl[np * 2][0] = t[0]; bl[np * 2][1] = t[1];
                bl[np * 2 + 1][0] = t[2]; bl[np * 2 + 1][1] = t[3];
            }
#pragma unroll
            for (int mi = 0; mi < 2; mi++)
#pragma unroll
                for (int ni = 0; ni < 4; ni++) {
                    mma_bf16(acc[mi][ni], ah[mi], bh[ni]);
                    mma_bf16(acc[mi][ni], ah[mi], bl[ni]);
                    mma_bf16(acc[mi][ni], al[mi], bh[ni]);
                }
        }
    }

    // ---- epilogue ----
    const int qrow = lane >> 2;
    const int qcol = 2 * (lane & 3);
#pragma unroll
    for (int mi = 0; mi < 2; mi++) {
#pragma unroll
        for (int ni = 0; ni < 4; ni++) {
            const int n = n0 + wn * 32 + ni * 8 + qcol;
            const float2 bv = *(const float2*)&bias[n];
#pragma unroll
            for (int hh = 0; hh < 2; hh++) {
                const int m = m0 + wm * 32 + mi * 16 + qrow + hh * 8;
                float2 v = make_float2(acc[mi][ni][2 * hh] + bv.x,
                                       acc[mi][ni][2 * hh + 1] + bv.y);
                if (EPI == 1) {
                    v.x = 0.5f * v.x * (1.f + erff(v.x * 0.70710678118654752f));
                    v.y = 0.5f * v.y * (1.f + erff(v.y * 0.70710678118654752f));
                }
                if (EPI == 2) {
                    float2 r = *(const float2*)&res[(size_t)m * N + n];
                    v.x += r.x; v.y += r.y;
                }
                *(float2*)&out[(size_t)m * N + n] = v;
            }
        }
    }
}

// ---------------------------------------------------------------------------
// LayerNorm: one warp per 256-wide row
// ---------------------------------------------------------------------------
__global__ __launch_bounds__(256)
void ln_k(const float* __restrict__ x, const float* __restrict__ g,
          const float* __restrict__ b, float* __restrict__ y)
{
    const int wid = threadIdx.x >> 5;
    const int lane = threadIdx.x & 31;
    const int row = blockIdx.x * 8 + wid;
    const float* xr = x + (size_t)row * KHID_;

    float v[8];
    float s = 0.f, s2 = 0.f;
#pragma unroll
    for (int i = 0; i < 8; i++) {
        v[i] = xr[lane + 32 * i];
        s += v[i];
        s2 += v[i] * v[i];
    }
#pragma unroll
    for (int o = 16; o; o >>= 1) {
        s += __shfl_xor_sync(0xffffffffu, s, o);
        s2 += __shfl_xor_sync(0xffffffffu, s2, o);
    }
    const float mu = s * (1.f / 256.f);
    const float var = s2 * (1.f / 256.f) - mu * mu;
    const float r = rsqrtf(var + 1e-5f);
    float* yr = y + (size_t)row * KHID_;
#pragma unroll
    for (int i = 0; i < 8; i++) {
        const int d = lane + 32 * i;
        yr[d] = (v[i] - mu) * r * g[d] + b[d];
    }
}

// ---------------------------------------------------------------------------
// Windowed attention (HISTORY=128) — round-3 version (111 us), unchanged
// ---------------------------------------------------------------------------
#define ATTN_SMEM_FLOATS (16896 + 8448)

__global__ __launch_bounds__(256, 2)
void attn_k(const float* __restrict__ qkv, float* __restrict__ h)
{
    extern __shared__ float sm[];
    float* Qs  = sm;
    float* Ks2 = sm + 8448;
    float* P   = sm;
    float* Vs  = sm + 16896;

    const int tid = threadIdx.x;
    const int tx = tid & 31;
    const int ty = tid >> 5;
    const int b  = blockIdx.x >> 6;
    const int qt = blockIdx.x & 63;
    const int t0 = qt * 64;
    const int g0 = b * KT_ + t0;
    const int kstart = (t0 >= HIST_) ? (t0 - HIST_) : 0;
    const int ntiles = (t0 + 64 - kstart) >> 6;

    const int lc  = tid & 127;
    const int lr0 = (tid >> 7) * 32;
    const int lt  = lc >> 1;
    const int lb  = lc & 1;
    const float scale = 0.0625f;

    float sreg[3][8][2];

#pragma unroll
    for (int kt = 0; kt < 3; kt++) {
        if (kt < ntiles) {
            const int kg0 = b * KT_ + kstart + kt * 64;
            unsigned long long acc2[8][2];
#pragma unroll
            for (int i = 0; i < 8; i++) { acc2[i][0] = 0ull; acc2[i][1] = 0ull; }

#pragma unroll
            for (int half = 0; half < 2; half++) {
                __syncthreads();
                for (int rr = 0; rr < 32; rr++) {
                    const int r = lr0 + rr;
                    Qs[r * 132 + lc] =
                        qkv[(size_t)(g0 + r) * 768 + half * 128 + lc] * scale;
                    Ks2[lt * 132 + 2 * r + lb] =
                        qkv[(size_t)(kg0 + r) * 768 + 256 + half * 128 + lc];
                }
                __syncthreads();
#pragma unroll 4
                for (int t = 0; t < 64; t += 2) {
                    ulonglong2 kv0 = *(const ulonglong2*)&Ks2[t * 132 + 4 * tx];
                    ulonglong2 kv1 = *(const ulonglong2*)&Ks2[(t + 1) * 132 + 4 * tx];
#pragma unroll
                    for (int i = 0; i < 8; i++) {
                        ulonglong2 qv =
                            *(const ulonglong2*)&Qs[(ty * 8 + i) * 132 + 2 * t];
                        acc2[i][0] = ffma2(qv.x, kv0.x, acc2[i][0]);
                        acc2[i][1] = ffma2(qv.x, kv0.y, acc2[i][1]);
                        acc2[i][0] = ffma2(qv.y, kv1.x, acc2[i][0]);
                        acc2[i][1] = ffma2(qv.y, kv1.y, acc2[i][1]);
                    }
                }
            }
#pragma unroll
            for (int i = 0; i < 8; i++) {
#pragma unroll
                for (int j = 0; j < 2; j++) {
                    float2 v = unpack2(acc2[i][j]);
                    const float s = v.x + v.y;
                    const int q = t0 + ty * 8 + i;
                    const int k = kstart + kt * 64 + 2 * tx + j;
                    const int d = q - k;
                    sreg[kt][i][j] = (d >= 0 && d <= HIST_) ? s : -3.0e38f;
                }
            }
        }
    }
    __syncthreads();

#pragma unroll
    for (int i = 0; i < 8; i++) {
        float mx = -3.0e38f;
#pragma unroll
        for (int kt = 0; kt < 3; kt++)
            if (kt < ntiles) {
                mx = fmaxf(mx, sreg[kt][i][0]);
                mx = fmaxf(mx, sreg[kt][i][1]);
            }
#pragma unroll
        for (int o = 16; o; o >>= 1)
            mx = fmaxf(mx, __shfl_xor_sync(0xffffffffu, mx, o));
        float sum = 0.f;
#pragma unroll
        for (int kt = 0; kt < 3; kt++)
            if (kt < ntiles) {
                const float e0 = __expf(sreg[kt][i][0] - mx);
                const float e1 = __expf(sreg[kt][i][1] - mx);
                sreg[kt][i][0] = e0;
                sreg[kt][i][1] = e1;
                sum += e0 + e1;
            }
#pragma unroll
        for (int o = 16; o; o >>= 1)
            sum += __shfl_xor_sync(0xffffffffu, sum, o);
        const float rinv = 1.0f / sum;
#pragma unroll
        for (int kt = 0; kt < 3; kt++)
            if (kt < ntiles) {
                float2 pv;
                pv.x = sreg[kt][i][0] * rinv;
                pv.y = sreg[kt][i][1] * rinv;
                *(float2*)&P[(ty * 8 + i) * 196 + kt * 64 + 2 * tx] = pv;
            }
    }

#pragma unroll
    for (int half = 0; half < 2; half++) {
        unsigned long long o2[8][2];
#pragma unroll
        for (int i = 0; i < 8; i++) { o2[i][0] = 0ull; o2[i][1] = 0ull; }

        for (int kt = 0; kt < ntiles; kt++) {
            const int kg0 = b * KT_ + kstart + kt * 64;
            __syncthreads();
            for (int rr = 0; rr < 32; rr++) {
                const int r = lr0 + rr;
                Vs[r * 132 + lc] =
                    qkv[(size_t)(kg0 + r) * 768 + 512 + half * 128 + lc];
            }
            __syncthreads();
#pragma unroll 2
            for (int jj = 0; jj < 64; jj += 4) {
                ulonglong2 vv0 = *(const ulonglong2*)&Vs[(jj + 0) * 132 + 4 * tx];
                ulonglong2 vv1 = *(const ulonglong2*)&Vs[(jj + 1) * 132 + 4 * tx];
                ulonglong2 vv2 = *(const ulonglong2*)&Vs[(jj + 2) * 132 + 4 * tx];
                ulonglong2 vv3 = *(const ulonglong2*)&Vs[(jj + 3) * 132 + 4 * tx];
#pragma unroll
                for (int i = 0; i < 8; i++) {
                    float4 p4 = *(const float4*)&P[(ty * 8 + i) * 196 + kt * 64 + jj];
                    unsigned long long p2;
                    p2 = pack2(p4.x, p4.x);
                    o2[i][0] = ffma2(p2, vv0.x, o2[i][0]);
                    o2[i][1] = ffma2(p2, vv0.y, o2[i][1]);
                    p2 = pack2(p4.y, p4.y);
                    o2[i][0] = ffma2(p2, vv1.x, o2[i][0]);
                    o2[i][1] = ffma2(p2, vv1.y, o2[i][1]);
                    p2 = pack2(p4.z, p4.z);
                    o2[i][0] = ffma2(p2, vv2.x, o2[i][0]);
                    o2[i][1] = ffma2(p2, vv2.y, o2[i][1]);
                    p2 = pack2(p4.w, p4.w);
                    o2[i][0] = ffma2(p2, vv3.x, o2[i][0]);
                    o2[i][1] = ffma2(p2, vv3.y, o2[i][1]);
                }
            }
        }
#pragma unroll
        for (int i = 0; i < 8; i++) {
            const size_t base =
                (size_t)(g0 + ty * 8 + i) * KHID_ + half * 128 + tx * 4;
            float4 hv = *(const float4*)&h[base];
            float2 a0 = unpack2(o2[i][0]);
            float2 a1 = unpack2(o2[i][1]);
            hv.x += a0.x; hv.y += a0.y; hv.z += a1.x; hv.w += a1.y;
            *(float4*)&h[base] = hv;
        }
    }
}

// ---------------------------------------------------------------------------
// Launch
// ---------------------------------------------------------------------------
extern "C" void kernel_launch(void* const* d_in, const int* in_sizes, int n_in,
                              void* d_out, int out_size)
{
    (void)in_sizes; (void)n_in; (void)out_size;
    const float* x       = (const float*)d_in[0];
    const float* W_in    = (const float*)d_in[1];
    const float* b_in    = (const float*)d_in[2];
    const float* W_qkv   = (const float*)d_in[3];
    const float* b_qkv   = (const float*)d_in[4];
    const float* g_attn  = (const float*)d_in[5];
    const float* be_attn = (const float*)d_in[6];
    const float* g_mlp   = (const float*)d_in[7];
    const float* be_mlp  = (const float*)d_in[8];
    const float* W1      = (const float*)d_in[9];
    const float* b1      = (const float*)d_in[10];
    const float* W2      = (const float*)d_in[11];
    const float* b2      = (const float*)d_in[12];
    const float* W_out   = (const float*)d_in[13];
    const float* b_out   = (const float*)d_in[14];
    float* out = (float*)d_out;

    float *h_p, *ln_p, *qkv_p, *m1_p;
    __nv_bfloat16 *whi, *wlo;
    cudaGetSymbolAddress((void**)&h_p, g_h);
    cudaGetSymbolAddress((void**)&ln_p, g_ln);
    cudaGetSymbolAddress((void**)&qkv_p, g_qkv);
    cudaGetSymbolAddress((void**)&m1_p, g_m1);
    cudaGetSymbolAddress((void**)&whi, g_whi);
    cudaGetSymbolAddress((void**)&wlo, g_wlo);

    const int attn_smem = ATTN_SMEM_FLOATS * 4;
    cudaFuncSetAttribute((const void*)attn_k,
                         cudaFuncAttributeMaxDynamicSharedMemorySize, attn_smem);
    const int gsm = 49152;   // Ahi/Alo 32KB + Bhi/Blo 16KB
    cudaFuncSetAttribute((const void*)gemm_mma<0>,
                         cudaFuncAttributeMaxDynamicSharedMemorySize, gsm);
    cudaFuncSetAttribute((const void*)gemm_mma<1>,
                         cudaFuncAttributeMaxDynamicSharedMemorySize, gsm);
    cudaFuncSetAttribute((const void*)gemm_mma<2>,
                         cudaFuncAttributeMaxDynamicSharedMemorySize, gsm);

    const dim3 blk(256);

    // 0) split + transpose all weights to bf16 hi/lo
    wsplit_k<<<(64 * 256 + 255) / 256, blk>>>(W_in, whi + OFF_IN_, wlo + OFF_IN_, 64, 256);
    wsplit_k<<<(256 * 768 + 255) / 256, blk>>>(W_qkv, whi + OFF_QKV_, wlo + OFF_QKV_, 256, 768);
    wsplit_k<<<(256 * 256 + 255) / 256, blk>>>(W1, whi + OFF_W1_, wlo + OFF_W1_, 256, 256);
    wsplit_k<<<(256 * 256 + 255) / 256, blk>>>(W2, whi + OFF_W2_, wlo + OFF_W2_, 256, 256);
    wsplit_k<<<(256 * 64 + 255) / 256, blk>>>(W_out, whi + OFF_OUT_, wlo + OFF_OUT_, 256, 64);

    // 1) h = x @ W_in + b_in                (K=64, N=256)
    gemm_mma<0><<<dim3(4, 128), blk, gsm>>>(
        x, whi + OFF_IN_, wlo + OFF_IN_, b_in, nullptr, h_p, KROWS_, 64, 256);

    // 2) ln = LN(h; g_attn, be_attn)
    ln_k<<<KROWS_ / 8, blk>>>(h_p, g_attn, be_attn, ln_p);

    // 3) qkv = ln @ W_qkv + b_qkv           (K=256, N=768)
    gemm_mma<0><<<dim3(12, 128), blk, gsm>>>(
        ln_p, whi + OFF_QKV_, wlo + OFF_QKV_, b_qkv, nullptr, qkv_p, KROWS_, 256, 768);

    // 4) h += window_attention(qkv)
    attn_k<<<KB_ * (KT_ / 64), blk, attn_smem>>>(qkv_p, h_p);

    // 5) ln = LN(h; g_mlp, be_mlp)
    ln_k<<<KROWS_ / 8, blk>>>(h_p, g_mlp, be_mlp, ln_p);

    // 6) m1 = gelu(ln @ W1 + b1)            (K=256, N=256)
    gemm_mma<1><<<dim3(4, 128), blk, gsm>>>(
        ln_p, whi + OFF_W1_, wlo + OFF_W1_, b1, nullptr, m1_p, KROWS_, 256, 256);

    // 7) h = h + (m1 @ W2 + b2)             (K=256, N=256)
    gemm_mma<2><<<dim3(4, 128), blk, gsm>>>(
        m1_p, whi + OFF_W2_, wlo + OFF_W2_, b2, h_p, h_p, KROWS_, 256, 256);

    // 8) out = h @ W_out + b_out            (K=256, N=64)
    gemm_mma<0><<<dim3(1, 128), blk, gsm>>>(
        h_p, whi + OFF_OUT_, wlo + OFF_OUT_, b_out, nullptr, out, KROWS_, 256, 64);
}

// round 6
// speedup vs baseline: 2.1096x; 1.2111x over previous
#include <cuda_runtime.h>
#include <cuda_bf16.h>
#include <math.h>
#include <stdint.h>

#define KB_ 4
#define KT_ 4096
#define KDIM_ 64
#define KHID_ 256
#define KROWS_ (KB_ * KT_)   // 16384
#define HIST_ 128

// Scratch (device globals; no allocation allowed)
__device__ float g_h[KROWS_ * KHID_];
__device__ float g_ln[KROWS_ * KHID_];
__device__ float g_qkv[KROWS_ * 3 * KHID_];
__device__ float g_m1[KROWS_ * KHID_];
// split-bf16 transposed weights: [N][K] hi/lo
#define OFF_IN_  0
#define OFF_QKV_ 16384
#define OFF_W1_  212992
#define OFF_W2_  278528
#define OFF_OUT_ 344064
#define WSPLIT_TOT_ 360448
__device__ __nv_bfloat16 g_whi[WSPLIT_TOT_];
__device__ __nv_bfloat16 g_wlo[WSPLIT_TOT_];

// ---------------------------------------------------------------------------
// PTX helpers (sm_80-era, compile for compute_103)
// ---------------------------------------------------------------------------
__device__ __forceinline__ uint32_t smem_u32(const void* p) {
    uint32_t a;
    asm("{ .reg .u64 t; cvta.to.shared.u64 t, %1; cvt.u32.u64 %0, t; }"
        : "=r"(a) : "l"(p));
    return a;
}
__device__ __forceinline__ void ldsm4(uint32_t* r, uint32_t a) {
    asm volatile("ldmatrix.sync.aligned.m8n8.x4.shared.b16 {%0,%1,%2,%3}, [%4];"
        : "=r"(r[0]), "=r"(r[1]), "=r"(r[2]), "=r"(r[3]) : "r"(a));
}
__device__ __forceinline__ void ldsm4t(uint32_t* r, uint32_t a) {
    asm volatile("ldmatrix.sync.aligned.m8n8.x4.trans.shared.b16 {%0,%1,%2,%3}, [%4];"
        : "=r"(r[0]), "=r"(r[1]), "=r"(r[2]), "=r"(r[3]) : "r"(a));
}
__device__ __forceinline__ void mma_bf16(float* d, const uint32_t* a,
                                         const uint32_t* b) {
    asm volatile(
        "mma.sync.aligned.m16n8k16.row.col.f32.bf16.bf16.f32 "
        "{%0,%1,%2,%3}, {%4,%5,%6,%7}, {%8,%9}, {%0,%1,%2,%3};"
        : "+f"(d[0]), "+f"(d[1]), "+f"(d[2]), "+f"(d[3])
        : "r"(a[0]), "r"(a[1]), "r"(a[2]), "r"(a[3]), "r"(b[0]), "r"(b[1]));
}
__device__ __forceinline__ uint32_t sw128(uint32_t off) {
    return off ^ ((off >> 3) & 0x70);
}

// ---------------------------------------------------------------------------
// Merged weight split: all 5 weights -> hi/lo [N][K] bf16 in ONE launch
// ---------------------------------------------------------------------------
__global__ __launch_bounds__(256)
void wsplit_all(const float* __restrict__ W_in, const float* __restrict__ W_qkv,
                const float* __restrict__ W1, const float* __restrict__ W2,
                const float* __restrict__ W_out,
                __nv_bfloat16* __restrict__ hi, __nv_bfloat16* __restrict__ lo)
{
    const int idx = blockIdx.x * 256 + threadIdx.x;
    const float* src;
    int off, N, K, local;
    if (idx < 16384)       { src = W_in;  off = OFF_IN_;  K = 64;  N = 256; local = idx; }
    else if (idx < 212992) { src = W_qkv; off = OFF_QKV_; K = 256; N = 768; local = idx - 16384; }
    else if (idx < 278528) { src = W1;    off = OFF_W1_;  K = 256; N = 256; local = idx - 212992; }
    else if (idx < 344064) { src = W2;    off = OFF_W2_;  K = 256; N = 256; local = idx - 278528; }
    else if (idx < 360448) { src = W_out; off = OFF_OUT_; K = 256; N = 64;  local = idx - 344064; }
    else return;
    const int k = local / N, n = local % N;
    const float a = src[local];
    const __nv_bfloat16 h = __float2bfloat16_rn(a);
    const float r = a - __bfloat162float(h);
    hi[off + (size_t)n * K + k] = h;
    lo[off + (size_t)n * K + k] = __float2bfloat16_rn(r);
}

// ---------------------------------------------------------------------------
// HMMA GEMM (split-bf16, fp32 accum) — unchanged from round 5 (passing)
// ---------------------------------------------------------------------------
template <int EPI>
__global__ __launch_bounds__(256)
void gemm_mma(const float* __restrict__ A, const __nv_bfloat16* __restrict__ Bhi,
              const __nv_bfloat16* __restrict__ Blo, const float* __restrict__ bias,
              const float* __restrict__ res, float* __restrict__ out,
              int M, int K, int N)
{
    extern __shared__ char smp[];
    const uint32_t sb = smem_u32(smp);
    constexpr uint32_t A_HI = 0, A_LO = 16384, B_HI = 32768, B_LO = 40960;

    const int tid = threadIdx.x, lane = tid & 31, w = tid >> 5;
    const int wm = w & 3, wn = w >> 2;
    const int m0 = blockIdx.y * 128, n0 = blockIdx.x * 64;

    float acc[2][4][4];
#pragma unroll
    for (int mi = 0; mi < 2; mi++)
#pragma unroll
        for (int ni = 0; ni < 4; ni++)
#pragma unroll
            for (int e = 0; e < 4; e++) acc[mi][ni][e] = 0.f;

    const int a_row_l  = lane & 15;
    const int a_kseg_l = lane >> 4;
    const int b_row_l  = ((lane >> 4) << 3) + (lane & 7);
    const int b_kseg_l = (lane >> 3) & 1;

    const int nchunks = K >> 6;
    for (int c = 0; c < nchunks; c++) {
        __syncthreads();
#pragma unroll
        for (int i = 0; i < 16; i++) {
            const int p = i * 256 + tid;
            const int row = p >> 5, kp = p & 31;
            float2 a = *(const float2*)&A[(size_t)(m0 + row) * K + c * 64 + 2 * kp];
            __nv_bfloat162 h2 = __floats2bfloat162_rn(a.x, a.y);
            const float rx = a.x - __bfloat162float(__low2bfloat16(h2));
            const float ry = a.y - __bfloat162float(__high2bfloat16(h2));
            __nv_bfloat162 l2 = __floats2bfloat162_rn(rx, ry);
            const uint32_t sw = sw128(row * 128 + kp * 4);
            *(__nv_bfloat162*)(smp + A_HI + sw) = h2;
            *(__nv_bfloat162*)(smp + A_LO + sw) = l2;
        }
#pragma unroll
        for (int i = 0; i < 2; i++) {
            const int u = i * 256 + tid;
            const int row = u >> 3, seg = u & 7;
            const uint32_t sw = sw128(row * 128 + seg * 16);
            const size_t gsrc = (size_t)(n0 + row) * K + c * 64 + seg * 8;
            *(uint4*)(smp + B_HI + sw) = *(const uint4*)&Bhi[gsrc];
            *(uint4*)(smp + B_LO + sw) = *(const uint4*)&Blo[gsrc];
        }
        __syncthreads();

#pragma unroll
        for (int ks = 0; ks < 4; ks++) {
            uint32_t ah[2][4], al[2][4], bh[4][2], bl[4][2];
#pragma unroll
            for (int mi = 0; mi < 2; mi++) {
                const int row = wm * 32 + mi * 16 + a_row_l;
                const uint32_t sw = sw128(row * 128 + (ks * 2 + a_kseg_l) * 16);
                ldsm4(ah[mi], sb + A_HI + sw);
                ldsm4(al[mi], sb + A_LO + sw);
            }
#pragma unroll
            for (int np = 0; np < 2; np++) {
                const int row = wn * 32 + np * 16 + b_row_l;
                const uint32_t sw = sw128(row * 128 + (ks * 2 + b_kseg_l) * 16);
                uint32_t t[4];
                ldsm4(t, sb + B_HI + sw);
                bh[np * 2][0] = t[0]; bh[np * 2][1] = t[1];
                bh[np * 2 + 1][0] = t[2]; bh[np * 2 + 1][1] = t[3];
                ldsm4(t, sb + B_LO + sw);
                bl[np * 2][0] = t[0]; bl[np * 2][1] = t[1];
                bl[np * 2 + 1][0] = t[2]; bl[np * 2 + 1][1] = t[3];
            }
#pragma unroll
            for (int mi = 0; mi < 2; mi++)
#pragma unroll
                for (int ni = 0; ni < 4; ni++) {
                    mma_bf16(acc[mi][ni], ah[mi], bh[ni]);
                    mma_bf16(acc[mi][ni], ah[mi], bl[ni]);
                    mma_bf16(acc[mi][ni], al[mi], bh[ni]);
                }
        }
    }

    const int qrow = lane >> 2;
    const int qcol = 2 * (lane & 3);
#pragma unroll
    for (int mi = 0; mi < 2; mi++) {
#pragma unroll
        for (int ni = 0; ni < 4; ni++) {
            const int n = n0 + wn * 32 + ni * 8 + qcol;
            const float2 bv = *(const float2*)&bias[n];
#pragma unroll
            for (int hh = 0; hh < 2; hh++) {
                const int m = m0 + wm * 32 + mi * 16 + qrow + hh * 8;
                float2 v = make_float2(acc[mi][ni][2 * hh] + bv.x,
                                       acc[mi][ni][2 * hh + 1] + bv.y);
                if (EPI == 1) {
                    v.x = 0.5f * v.x * (1.f + erff(v.x * 0.70710678118654752f));
                    v.y = 0.5f * v.y * (1.f + erff(v.y * 0.70710678118654752f));
                }
                if (EPI == 2) {
                    float2 r = *(const float2*)&res[(size_t)m * N + n];
                    v.x += r.x; v.y += r.y;
                }
                *(float2*)&out[(size_t)m * N + n] = v;
            }
        }
    }
}

// ---------------------------------------------------------------------------
// LayerNorm: one warp per 256-wide row
// ---------------------------------------------------------------------------
__global__ __launch_bounds__(256)
void ln_k(const float* __restrict__ x, const float* __restrict__ g,
          const float* __restrict__ b, float* __restrict__ y)
{
    const int wid = threadIdx.x >> 5;
    const int lane = threadIdx.x & 31;
    const int row = blockIdx.x * 8 + wid;
    const float* xr = x + (size_t)row * KHID_;

    float v[8];
    float s = 0.f, s2 = 0.f;
#pragma unroll
    for (int i = 0; i < 8; i++) {
        v[i] = xr[lane + 32 * i];
        s += v[i];
        s2 += v[i] * v[i];
    }
#pragma unroll
    for (int o = 16; o; o >>= 1) {
        s += __shfl_xor_sync(0xffffffffu, s, o);
        s2 += __shfl_xor_sync(0xffffffffu, s2, o);
    }
    const float mu = s * (1.f / 256.f);
    const float var = s2 * (1.f / 256.f) - mu * mu;
    const float r = rsqrtf(var + 1e-5f);
    float* yr = y + (size_t)row * KHID_;
#pragma unroll
    for (int i = 0; i < 8; i++) {
        const int d = lane + 32 * i;
        yr[d] = (v[i] - mu) * r * g[d] + b[d];
    }
}

// ---------------------------------------------------------------------------
// HMMA windowed attention (HISTORY=128). 64 queries/block, 8 warps.
// Split-bf16 (hi/lo, 3 products) for QK^T and P·V, fp32 accumulation.
// Phase 1 (QK): warps 4m x 2n; d in 4 chunks of 64; S frags in regs.
// Softmax: quad-shfl + smem cross-warp reduce; P split to smem panels.
// Phase 2 (PV): warps 2m x 4n over d-halves; V via ldmatrix.x4.trans.
// smem (bytes): QC hi/lo 0/8192, KC hi/lo 16384/24576 (phase 1);
//   P hi 0..24576 (3 panels), P lo 24576..49152 (overlays QC/KC);
//   V hi 49152..65536, V lo 65536..81920; red 81920..82944.
// ---------------------------------------------------------------------------
#define ATTN_SMEM_BYTES 82944

__global__ __launch_bounds__(256)
void attn_k(const float* __restrict__ qkv, float* __restrict__ h)
{
    extern __shared__ char smp[];
    const uint32_t sb = smem_u32(smp);
    constexpr uint32_t QC_HI = 0, QC_LO = 8192, KC_HI = 16384, KC_LO = 24576;
    constexpr uint32_t P_HI = 0, P_LO = 24576, V_HI = 49152, V_LO = 65536;
    float* redm = (float*)(smp + 81920);   // [64][2]
    float* reds = (float*)(smp + 82432);   // [64][2]

    const int tid = threadIdx.x, lane = tid & 31, w = tid >> 5;
    const int b  = blockIdx.x >> 6;
    const int qt = blockIdx.x & 63;
    const int t0 = qt * 64;
    const int g0 = b * KT_ + t0;
    const int kstart = (t0 >= HIST_) ? (t0 - HIST_) : 0;
    const int ntiles = (t0 + 64 - kstart) >> 6;    // 1..3
    const float scale = 0.0625f;

    // ---------------- Phase 1: S = Q K^T ----------------
    const int wm = w & 3, wn = w >> 2;
    const int a_row_l  = lane & 15;
    const int a_kseg_l = lane >> 4;
    const int b_row_l  = ((lane >> 4) << 3) + (lane & 7);
    const int b_kseg_l = (lane >> 3) & 1;

    float sreg[3][4][4];
#pragma unroll
    for (int kt = 0; kt < 3; kt++)
#pragma unroll
        for (int ni = 0; ni < 4; ni++)
#pragma unroll
            for (int e = 0; e < 4; e++) sreg[kt][ni][e] = 0.f;

    for (int c = 0; c < 4; c++) {
        for (int kt = 0; kt < ntiles; kt++) {
            const int kg0 = b * KT_ + kstart + kt * 64;
            __syncthreads();
            if (kt == 0) {   // stage Q chunk [64][64]
#pragma unroll
                for (int i = 0; i < 8; i++) {
                    const int idx = i * 256 + tid;
                    const int row = idx >> 5, c2 = idx & 31;
                    float2 a = *(const float2*)&qkv[(size_t)(g0 + row) * 768 + c * 64 + 2 * c2];
                    __nv_bfloat162 h2 = __floats2bfloat162_rn(a.x, a.y);
                    const float rx = a.x - __bfloat162float(__low2bfloat16(h2));
                    const float ry = a.y - __bfloat162float(__high2bfloat16(h2));
                    const uint32_t sw = sw128(row * 128 + c2 * 4);
                    *(__nv_bfloat162*)(smp + QC_HI + sw) = h2;
                    *(__nv_bfloat162*)(smp + QC_LO + sw) = __floats2bfloat162_rn(rx, ry);
                }
            }
            // stage K chunk [64][64]
#pragma unroll
            for (int i = 0; i < 8; i++) {
                const int idx = i * 256 + tid;
                const int row = idx >> 5, c2 = idx & 31;
                float2 a = *(const float2*)&qkv[(size_t)(kg0 + row) * 768 + 256 + c * 64 + 2 * c2];
                __nv_bfloat162 h2 = __floats2bfloat162_rn(a.x, a.y);
                const float rx = a.x - __bfloat162float(__low2bfloat16(h2));
                const float ry = a.y - __bfloat162float(__high2bfloat16(h2));
                const uint32_t sw = sw128(row * 128 + c2 * 4);
                *(__nv_bfloat162*)(smp + KC_HI + sw) = h2;
                *(__nv_bfloat162*)(smp + KC_LO + sw) = __floats2bfloat162_rn(rx, ry);
            }
            __syncthreads();

#pragma unroll
            for (int ks = 0; ks < 4; ks++) {
                uint32_t qh[4], ql[4], kh[4][2], kl[4][2];
                {
                    const int row = wm * 16 + a_row_l;
                    const uint32_t sw = sw128(row * 128 + (ks * 2 + a_kseg_l) * 16);
                    ldsm4(qh, sb + QC_HI + sw);
                    ldsm4(ql, sb + QC_LO + sw);
                }
#pragma unroll
                for (int np = 0; np < 2; np++) {
                    const int row = wn * 32 + np * 16 + b_row_l;
                    const uint32_t sw = sw128(row * 128 + (ks * 2 + b_kseg_l) * 16);
                    uint32_t t[4];
                    ldsm4(t, sb + KC_HI + sw);
                    kh[np * 2][0] = t[0]; kh[np * 2][1] = t[1];
                    kh[np * 2 + 1][0] = t[2]; kh[np * 2 + 1][1] = t[3];
                    ldsm4(t, sb + KC_LO + sw);
                    kl[np * 2][0] = t[0]; kl[np * 2][1] = t[1];
                    kl[np * 2 + 1][0] = t[2]; kl[np * 2 + 1][1] = t[3];
                }
#pragma unroll
                for (int ni = 0; ni < 4; ni++) {
                    mma_bf16(sreg[kt][ni], qh, kh[ni]);
                    mma_bf16(sreg[kt][ni], qh, kl[ni]);
                    mma_bf16(sreg[kt][ni], ql, kh[ni]);
                }
            }
        }
    }

    // ---------------- finalize: scale + mask ----------------
    const int qr0 = wm * 16 + (lane >> 2);       // rows qr0, qr0+8
#pragma unroll
    for (int kt = 0; kt < 3; kt++)
        if (kt < ntiles)
#pragma unroll
            for (int ni = 0; ni < 4; ni++)
#pragma unroll
                for (int e = 0; e < 4; e++) {
                    const int qrow = t0 + qr0 + 8 * (e >> 1);
                    const int key = kstart + kt * 64 + wn * 32 + ni * 8 + (lane & 3) * 2 + (e & 1);
                    const int d = qrow - key;
                    sreg[kt][ni][e] = (d >= 0 && d <= HIST_)
                                      ? sreg[kt][ni][e] * scale : -3.0e38f;
                }

    // ---------------- softmax ----------------
    float mx[2] = {-3.0e38f, -3.0e38f};
#pragma unroll
    for (int kt = 0; kt < 3; kt++)
        if (kt < ntiles)
#pragma unroll
            for (int ni = 0; ni < 4; ni++)
#pragma unroll
                for (int e = 0; e < 4; e++)
                    mx[e >> 1] = fmaxf(mx[e >> 1], sreg[kt][ni][e]);
#pragma unroll
    for (int o = 1; o <= 2; o <<= 1) {
        mx[0] = fmaxf(mx[0], __shfl_xor_sync(0xffffffffu, mx[0], o));
        mx[1] = fmaxf(mx[1], __shfl_xor_sync(0xffffffffu, mx[1], o));
    }
    if ((lane & 3) == 0) {
        redm[qr0 * 2 + wn] = mx[0];
        redm[(qr0 + 8) * 2 + wn] = mx[1];
    }
    __syncthreads();
    const float M0 = fmaxf(redm[qr0 * 2], redm[qr0 * 2 + 1]);
    const float M1 = fmaxf(redm[(qr0 + 8) * 2], redm[(qr0 + 8) * 2 + 1]);
    float sum[2] = {0.f, 0.f};
#pragma unroll
    for (int kt = 0; kt < 3; kt++)
        if (kt < ntiles)
#pragma unroll
            for (int ni = 0; ni < 4; ni++)
#pragma unroll
                for (int e = 0; e < 4; e++) {
                    const float ex = __expf(sreg[kt][ni][e] - ((e >> 1) ? M1 : M0));
                    sreg[kt][ni][e] = ex;
                    sum[e >> 1] += ex;
                }
#pragma unroll
    for (int o = 1; o <= 2; o <<= 1) {
        sum[0] += __shfl_xor_sync(0xffffffffu, sum[0], o);
        sum[1] += __shfl_xor_sync(0xffffffffu, sum[1], o);
    }
    if ((lane & 3) == 0) {
        reds[qr0 * 2 + wn] = sum[0];
        reds[(qr0 + 8) * 2 + wn] = sum[1];
    }
    __syncthreads();
    const float R0 = 1.f / (reds[qr0 * 2] + reds[qr0 * 2 + 1]);
    const float R1 = 1.f / (reds[(qr0 + 8) * 2] + reds[(qr0 + 8) * 2 + 1]);

    // write P panels (normalized, split hi/lo) — overlays QC/KC (post-sync)
#pragma unroll
    for (int kt = 0; kt < 3; kt++)
        if (kt < ntiles)
#pragma unroll
            for (int ni = 0; ni < 4; ni++)
#pragma unroll
                for (int hh = 0; hh < 2; hh++) {
                    const float rv = hh ? R1 : R0;
                    const float p0 = sreg[kt][ni][2 * hh] * rv;
                    const float p1 = sreg[kt][ni][2 * hh + 1] * rv;
                    __nv_bfloat162 h2 = __floats2bfloat162_rn(p0, p1);
                    const float r0 = p0 - __bfloat162float(__low2bfloat16(h2));
                    const float r1 = p1 - __bfloat162float(__high2bfloat16(h2));
                    const int row = qr0 + 8 * hh;
                    const int col = wn * 32 + ni * 8 + (lane & 3) * 2;
                    const uint32_t sw = sw128(row * 128 + col * 2);
                    *(__nv_bfloat162*)(smp + P_HI + kt * 8192 + sw) = h2;
                    *(__nv_bfloat162*)(smp + P_LO + kt * 8192 + sw) =
                        __floats2bfloat162_rn(r0, r1);
                }

    // ---------------- Phase 2: O = P V ----------------
    const int wm2 = w & 1, wn2 = w >> 1;
#pragma unroll
    for (int half = 0; half < 2; half++) {
        float o[2][4][4];
#pragma unroll
        for (int mi = 0; mi < 2; mi++)
#pragma unroll
            for (int ni = 0; ni < 4; ni++)
#pragma unroll
                for (int e = 0; e < 4; e++) o[mi][ni][e] = 0.f;

        for (int kt = 0; kt < ntiles; kt++) {
            const int kg0 = b * KT_ + kstart + kt * 64;
            __syncthreads();
            // stage V [64 keys][128 d] as two 64-wide panels, split hi/lo
#pragma unroll
            for (int i = 0; i < 16; i++) {
                const int idx = i * 256 + tid;
                const int row = idx >> 6, c2 = idx & 63;
                float2 a = *(const float2*)
                    &qkv[(size_t)(kg0 + row) * 768 + 512 + half * 128 + 2 * c2];
                __nv_bfloat162 h2 = __floats2bfloat162_rn(a.x, a.y);
                const float rx = a.x - __bfloat162float(__low2bfloat16(h2));
                const float ry = a.y - __bfloat162float(__high2bfloat16(h2));
                const int panel = c2 >> 5, pc2 = c2 & 31;
                const uint32_t sw = panel * 8192 + sw128(row * 128 + pc2 * 4);
                *(__nv_bfloat162*)(smp + V_HI + sw) = h2;
                *(__nv_bfloat162*)(smp + V_LO + sw) = __floats2bfloat162_rn(rx, ry);
            }
            __syncthreads();

#pragma unroll
            for (int ks = 0; ks < 4; ks++) {
                uint32_t ph[2][4], pl[2][4], vh[4][2], vl[4][2];
#pragma unroll
                for (int mi = 0; mi < 2; mi++) {
                    const int row = wm2 * 32 + mi * 16 + a_row_l;
                    const uint32_t sw = sw128(row * 128 + (ks * 2 + a_kseg_l) * 16);
                    ldsm4(ph[mi], sb + P_HI + kt * 8192 + sw);
                    ldsm4(pl[mi], sb + P_LO + kt * 8192 + sw);
                }
#pragma unroll
                for (int g = 0; g < 2; g++) {
                    const int dcol = wn2 * 32 + g * 16 + (lane >> 4) * 8; // +colgroup
                    const int key = ks * 16 + (lane & 7) + ((lane >> 3) & 1) * 8;
                    const int panel = dcol >> 6;
                    const uint32_t sw =
                        panel * 8192 + sw128(key * 128 + (dcol & 63) * 2);
                    uint32_t t[4];
                    ldsm4t(t, sb + V_HI + sw);
                    vh[g * 2][0] = t[0]; vh[g * 2][1] = t[1];
                    vh[g * 2 + 1][0] = t[2]; vh[g * 2 + 1][1] = t[3];
                    ldsm4t(t, sb + V_LO + sw);
                    vl[g * 2][0] = t[0]; vl[g * 2][1] = t[1];
                    vl[g * 2 + 1][0] = t[2]; vl[g * 2 + 1][1] = t[3];
                }
#pragma unroll
                for (int mi = 0; mi < 2; mi++)
#pragma unroll
                    for (int ni = 0; ni < 4; ni++) {
                        mma_bf16(o[mi][ni], ph[mi], vh[ni]);
                        mma_bf16(o[mi][ni], ph[mi], vl[ni]);
                        mma_bf16(o[mi][ni], pl[mi], vh[ni]);
                    }
            }
        }
        // epilogue: h += O (residual fused)
#pragma unroll
        for (int mi = 0; mi < 2; mi++)
#pragma unroll
            for (int ni = 0; ni < 4; ni++) {
                const int col = half * 128 + wn2 * 32 + ni * 8 + (lane & 3) * 2;
#pragma unroll
                for (int hh = 0; hh < 2; hh++) {
                    const int row = wm2 * 32 + mi * 16 + (lane >> 2) + 8 * hh;
                    float2 hv = *(const float2*)&h[(size_t)(g0 + row) * KHID_ + col];
                    hv.x += o[mi][ni][2 * hh];
                    hv.y += o[mi][ni][2 * hh + 1];
                    *(float2*)&h[(size_t)(g0 + row) * KHID_ + col] = hv;
                }
            }
    }
}

// ---------------------------------------------------------------------------
// Launch
// ---------------------------------------------------------------------------
extern "C" void kernel_launch(void* const* d_in, const int* in_sizes, int n_in,
                              void* d_out, int out_size)
{
    (void)in_sizes; (void)n_in; (void)out_size;
    const float* x       = (const float*)d_in[0];
    const float* W_in    = (const float*)d_in[1];
    const float* b_in    = (const float*)d_in[2];
    const float* W_qkv   = (const float*)d_in[3];
    const float* b_qkv   = (const float*)d_in[4];
    const float* g_attn  = (const float*)d_in[5];
    const float* be_attn = (const float*)d_in[6];
    const float* g_mlp   = (const float*)d_in[7];
    const float* be_mlp  = (const float*)d_in[8];
    const float* W1      = (const float*)d_in[9];
    const float* b1      = (const float*)d_in[10];
    const float* W2      = (const float*)d_in[11];
    const float* b2      = (const float*)d_in[12];
    const float* W_out   = (const float*)d_in[13];
    const float* b_out   = (const float*)d_in[14];
    float* out = (float*)d_out;

    float *h_p, *ln_p, *qkv_p, *m1_p;
    __nv_bfloat16 *whi, *wlo;
    cudaGetSymbolAddress((void**)&h_p, g_h);
    cudaGetSymbolAddress((void**)&ln_p, g_ln);
    cudaGetSymbolAddress((void**)&qkv_p, g_qkv);
    cudaGetSymbolAddress((void**)&m1_p, g_m1);
    cudaGetSymbolAddress((void**)&whi, g_whi);
    cudaGetSymbolAddress((void**)&wlo, g_wlo);

    cudaFuncSetAttribute((const void*)attn_k,
                         cudaFuncAttributeMaxDynamicSharedMemorySize, ATTN_SMEM_BYTES);
    const int gsm = 49152;
    cudaFuncSetAttribute((const void*)gemm_mma<0>,
                         cudaFuncAttributeMaxDynamicSharedMemorySize, gsm);
    cudaFuncSetAttribute((const void*)gemm_mma<1>,
                         cudaFuncAttributeMaxDynamicSharedMemorySize, gsm);
    cudaFuncSetAttribute((const void*)gemm_mma<2>,
                         cudaFuncAttributeMaxDynamicSharedMemorySize, gsm);

    const dim3 blk(256);

    // 0) split + transpose all weights (single launch)
    wsplit_all<<<(WSPLIT_TOT_ + 255) / 256, blk>>>(W_in, W_qkv, W1, W2, W_out, whi, wlo);

    // 1) h = x @ W_in + b_in
    gemm_mma<0><<<dim3(4, 128), blk, gsm>>>(
        x, whi + OFF_IN_, wlo + OFF_IN_, b_in, nullptr, h_p, KROWS_, 64, 256);

    // 2) ln = LN(h; g_attn, be_attn)
    ln_k<<<KROWS_ / 8, blk>>>(h_p, g_attn, be_attn, ln_p);

    // 3) qkv = ln @ W_qkv + b_qkv
    gemm_mma<0><<<dim3(12, 128), blk, gsm>>>(
        ln_p, whi + OFF_QKV_, wlo + OFF_QKV_, b_qkv, nullptr, qkv_p, KROWS_, 256, 768);

    // 4) h += window_attention(qkv)
    attn_k<<<KB_ * (KT_ / 64), blk, ATTN_SMEM_BYTES>>>(qkv_p, h_p);

    // 5) ln = LN(h; g_mlp, be_mlp)
    ln_k<<<KROWS_ / 8, blk>>>(h_p, g_mlp, be_mlp, ln_p);

    // 6) m1 = gelu(ln @ W1 + b1)
    gemm_mma<1><<<dim3(4, 128), blk, gsm>>>(
        ln_p, whi + OFF_W1_, wlo + OFF_W1_, b1, nullptr, m1_p, KROWS_, 256, 256);

    // 7) h = h + (m1 @ W2 + b2)
    gemm_mma<2><<<dim3(4, 128), blk, gsm>>>(
        m1_p, whi + OFF_W2_, wlo + OFF_W2_, b2, h_p, h_p, KROWS_, 256, 256);

    // 8) out = h @ W_out + b_out
    gemm_mma<0><<<dim3(1, 128), blk, gsm>>>(
        h_p, whi + OFF_OUT_, wlo + OFF_OUT_, b_out, nullptr, out, KROWS_, 256, 64);
}